// round 1
// baseline (speedup 1.0000x reference)
#include <cuda_runtime.h>
#include <cuda_bf16.h>
#include <math.h>

// ---------------- problem constants ----------------
#define BB   64      // batch
#define TT   512     // seq len
#define DD   512     // input dim (2H)
#define HH   256     // hidden
#define MS   64      // max slots
#define ML   8       // max span len
#define NST  64      // slot types
#define G4   1024    // 4H gates per direction
#define NCOL 2048    // gates both directions
#define NSPAN (BB*MS)        // 4096
#define NPOS  (NSPAN*ML)     // 32768 worst-case valid positions

// ---------------- device scratch (static, allowed) ----------------
__device__ int   d_nvalid;
__device__ int   d_actcount[8];
__device__ int   d_len_g[NSPAN];
__device__ int   d_srcidx_g[NPOS];           // gather row (b*T+t) per valid pos
__device__ int   d_rowidx_g[NPOS];           // dest row (span*8+rank) per valid pos
__device__ int   d_actlist_g[8][NSPAN];      // spans active at step t (t=1..7)
__device__ float d_Wt[DD*NCOL];              // [k][n] transposed concat W_ih
__device__ float d_bcat[NCOL];
__device__ float d_WhhT[HH*NCOL];            // [k][dir*1024+g]
__device__ float d_sembT[DD*NST];            // [k][slot]
__device__ float d_XG[(size_t)NPOS*NCOL];    // 256 MB: input gates per valid (span,rank)
__device__ float d_G[(size_t)NSPAN*NCOL];    // recurrent gate contribution per step
__device__ float d_h[NSPAN*2*HH];
__device__ float d_c[NSPAN*2*HH];
__device__ float d_pooled[NSPAN*2*HH];       // [span][dir*256+j]

__device__ __forceinline__ float sigf(float x){ return 1.0f/(1.0f+expf(-x)); }

// ---------------- init ----------------
__global__ void k_init(){
    if (threadIdx.x == 0) d_nvalid = 0;
    if (threadIdx.x < 8)  d_actcount[threadIdx.x] = 0;
}

// ---------------- span packing (replicates JAX _pack_spans) ----------------
__global__ void k_pack(const int* __restrict__ bio){
    int b = blockIdx.x;
    __shared__ int s_tok[MS][ML];
    __shared__ int s_cnt[MS];
    int tid = threadIdx.x;          // blockDim = 64
    s_cnt[tid] = 0;
    __syncthreads();
    if (tid == 0){
        int sid = -1;
        const int* bb = bio + b*TT;
        for (int t = 0; t < TT; t++){
            int tag = bb[t];
            if (tag == 1) sid++;
            if ((tag == 1 || tag == 2) && sid >= 0 && sid < MS){
                int r = s_cnt[sid];
                if (r < ML) s_tok[sid][r] = t;
                s_cnt[sid] = r + 1;
            }
        }
    }
    __syncthreads();
    int s = tid;
    int len = min(s_cnt[s], ML);
    int span = b*MS + s;
    d_len_g[span] = len;
    if (len > 0){
        int base = atomicAdd(&d_nvalid, len);
        for (int r = 0; r < len; r++){
            d_srcidx_g[base+r] = b*TT + s_tok[s][r];
            d_rowidx_g[base+r] = span*ML + r;
        }
        for (int t = 1; t < ML; t++){
            if (len > t){
                int k = atomicAdd(&d_actcount[t], 1);
                d_actlist_g[t][k] = span;
            }
        }
    }
}

// ---------------- weight prep (transposes) ----------------
__global__ void k_prep(const float* __restrict__ Wih_f, const float* __restrict__ Wih_b,
                       const float* __restrict__ bf,    const float* __restrict__ bbias,
                       const float* __restrict__ Whh_f, const float* __restrict__ Whh_b,
                       const float* __restrict__ semb){
    int i = blockIdx.x*blockDim.x + threadIdx.x;
    int stride = gridDim.x*blockDim.x;
    for (int idx = i; idx < DD*NCOL; idx += stride){
        int k = idx >> 11, n = idx & (NCOL-1);
        int dir = n >> 10, g = n & (G4-1);
        d_Wt[idx] = dir ? Wih_b[g*DD + k] : Wih_f[g*DD + k];
    }
    for (int idx = i; idx < HH*NCOL; idx += stride){
        int k = idx >> 11, n = idx & (NCOL-1);
        int dir = n >> 10, g = n & (G4-1);
        d_WhhT[idx] = dir ? Whh_b[g*HH + k] : Whh_f[g*HH + k];
    }
    for (int idx = i; idx < NCOL; idx += stride)
        d_bcat[idx] = (idx < G4) ? bf[idx] : bbias[idx - G4];
    for (int idx = i; idx < DD*NST; idx += stride){
        int k = idx / NST, n = idx % NST;
        d_sembT[idx] = semb[n*DD + k];
    }
}

// ---------------- xg GEMM: gathered X [M,512] x Wt [512,2048] + b ----------------
__global__ void k_xg_gemm(const float* __restrict__ X){
    const int BM=128, BN=128, BK=16;
    int M = d_nvalid;
    int mBase = blockIdx.y * BM;
    if (mBase >= M) return;
    int nBase = blockIdx.x * BN;
    __shared__ float As[BK][BM];
    __shared__ float Bs[BK][BN];
    __shared__ int sidx[BM];
    __shared__ int ridx[BM];
    int tid = threadIdx.x;
    if (tid < BM){
        int m = mBase + tid;
        bool v = (m < M);
        sidx[tid] = v ? d_srcidx_g[m]*DD : 0;
        ridx[tid] = v ? d_rowidx_g[m] : -1;
    }
    __syncthreads();
    float acc[8][8];
    #pragma unroll
    for (int i=0;i<8;i++)
        #pragma unroll
        for (int j=0;j<8;j++) acc[i][j]=0.f;
    int ty = tid >> 4, tx = tid & 15;
    for (int k0 = 0; k0 < DD; k0 += BK){
        #pragma unroll
        for (int li = 0; li < 2; li++){
            int lin = tid + li*256;
            int row = lin >> 2;
            int kq  = (lin & 3) * 4;
            float4 v = *reinterpret_cast<const float4*>(X + sidx[row] + k0 + kq);
            As[kq+0][row]=v.x; As[kq+1][row]=v.y; As[kq+2][row]=v.z; As[kq+3][row]=v.w;
        }
        #pragma unroll
        for (int li = 0; li < 2; li++){
            int lin = tid + li*256;
            int kb = lin >> 5;
            int nq = (lin & 31) * 4;
            *reinterpret_cast<float4*>(&Bs[kb][nq]) =
                *reinterpret_cast<const float4*>(d_Wt + (size_t)(k0+kb)*NCOL + nBase + nq);
        }
        __syncthreads();
        #pragma unroll
        for (int kk = 0; kk < BK; kk++){
            float a[8], b[8];
            *reinterpret_cast<float4*>(a)   = *reinterpret_cast<float4*>(&As[kk][ty*8]);
            *reinterpret_cast<float4*>(a+4) = *reinterpret_cast<float4*>(&As[kk][ty*8+4]);
            *reinterpret_cast<float4*>(b)   = *reinterpret_cast<float4*>(&Bs[kk][tx*8]);
            *reinterpret_cast<float4*>(b+4) = *reinterpret_cast<float4*>(&Bs[kk][tx*8+4]);
            #pragma unroll
            for (int i=0;i<8;i++)
                #pragma unroll
                for (int j=0;j<8;j++) acc[i][j] += a[i]*b[j];
        }
        __syncthreads();
    }
    #pragma unroll
    for (int i=0;i<8;i++){
        int r = ty*8 + i;
        int crow = ridx[r];
        if (crow < 0) continue;
        size_t base = (size_t)crow*NCOL + nBase + tx*8;
        #pragma unroll
        for (int j=0;j<8;j++)
            d_XG[base+j] = acc[i][j] + d_bcat[nBase + tx*8 + j];
    }
}

// ---------------- per-step recurrent GEMM: h[active,256] x WhhT[256,1024] ----------------
__global__ void k_step_gemm(int t){
    const int BM=64, BN=64, BK=16;
    int cnt = d_actcount[t];
    int mBase = blockIdx.y * BM;
    if (mBase >= cnt) return;
    int dir = blockIdx.z;
    int nBase = blockIdx.x * BN;
    __shared__ float As[BK][BM];
    __shared__ float Bs[BK][BN];
    __shared__ int aoff[BM];
    __shared__ int spn[BM];
    int tid = threadIdx.x;
    if (tid < BM){
        int m = mBase + tid;
        bool v = (m < cnt);
        int span = v ? d_actlist_g[t][m] : 0;
        aoff[tid] = (span*2 + dir)*HH;
        spn[tid]  = v ? span : -1;
    }
    __syncthreads();
    float acc[4][4];
    #pragma unroll
    for (int i=0;i<4;i++)
        #pragma unroll
        for (int j=0;j<4;j++) acc[i][j]=0.f;
    int ty = tid >> 4, tx = tid & 15;
    for (int k0 = 0; k0 < HH; k0 += BK){
        {
            int row = tid >> 2;
            int kq  = (tid & 3) * 4;
            float4 v = *reinterpret_cast<const float4*>(d_h + aoff[row] + k0 + kq);
            As[kq+0][row]=v.x; As[kq+1][row]=v.y; As[kq+2][row]=v.z; As[kq+3][row]=v.w;
        }
        {
            int kb = tid >> 4;
            int nq = (tid & 15) * 4;
            *reinterpret_cast<float4*>(&Bs[kb][nq]) =
                *reinterpret_cast<const float4*>(d_WhhT + (size_t)(k0+kb)*NCOL + dir*G4 + nBase + nq);
        }
        __syncthreads();
        #pragma unroll
        for (int kk=0; kk<BK; kk++){
            float a[4], b[4];
            *reinterpret_cast<float4*>(a) = *reinterpret_cast<float4*>(&As[kk][ty*4]);
            *reinterpret_cast<float4*>(b) = *reinterpret_cast<float4*>(&Bs[kk][tx*4]);
            #pragma unroll
            for (int i=0;i<4;i++)
                #pragma unroll
                for (int j=0;j<4;j++) acc[i][j] += a[i]*b[j];
        }
        __syncthreads();
    }
    #pragma unroll
    for (int i=0;i<4;i++){
        int r = ty*4 + i;
        int span = spn[r];
        if (span < 0) continue;
        size_t base = (size_t)span*NCOL + dir*G4 + nBase + tx*4;
        #pragma unroll
        for (int j=0;j<4;j++) d_G[base+j] = acc[i][j];
    }
}

// ---------------- LSTM pointwise: step 0 (h=c=0 prior, initializes pooled) ----------------
__global__ void k_step0(){
    int span = blockIdx.x;
    int dir  = blockIdx.y;
    int j    = threadIdx.x;
    int len  = d_len_g[span];
    int hidx = (span*2 + dir)*HH + j;
    int pidx = span*2*HH + dir*HH + j;
    if (len == 0){
        d_h[hidx] = 0.f; d_c[hidx] = 0.f; d_pooled[pidx] = 0.f;
        return;
    }
    int rank = dir ? (len-1) : 0;
    const float* xg = d_XG + (size_t)(span*ML + rank)*NCOL + dir*G4;
    float gi = xg[j], gf = xg[HH+j], gg = xg[2*HH+j], go = xg[3*HH+j];
    (void)gf;
    float c = sigf(gi) * tanhf(gg);         // f*0 term vanishes
    float h = sigf(go) * tanhf(c);
    d_c[hidx] = c; d_h[hidx] = h; d_pooled[pidx] = h;
}

// ---------------- LSTM pointwise: steps 1..7 ----------------
__global__ void k_step(int t){
    int m = blockIdx.x;
    if (m >= d_actcount[t]) return;
    int dir = blockIdx.y;
    int j = threadIdx.x;
    int span = d_actlist_g[t][m];
    int len  = d_len_g[span];
    int rank = dir ? (len-1-t) : t;
    const float* xg = d_XG + (size_t)(span*ML + rank)*NCOL + dir*G4;
    const float* gr = d_G  + (size_t)span*NCOL + dir*G4;
    float gi = xg[j]      + gr[j];
    float gf = xg[HH+j]   + gr[HH+j];
    float gg = xg[2*HH+j] + gr[2*HH+j];
    float go = xg[3*HH+j] + gr[3*HH+j];
    int hidx = (span*2 + dir)*HH + j;
    float c = d_c[hidx];
    c = sigf(gf)*c + sigf(gi)*tanhf(gg);
    float h = sigf(go)*tanhf(c);
    d_c[hidx] = c; d_h[hidx] = h;
    d_pooled[span*2*HH + dir*HH + j] += h;
}

// ---------------- scoring GEMM: pooled [4096,512] x sembT [512,64] ----------------
__global__ void k_score(float* __restrict__ out){
    const int BM=64, BN=64, BK=16;
    int mBase = blockIdx.x * BM;
    __shared__ float As[BK][BM];
    __shared__ float Bs[BK][BN];
    int tid = threadIdx.x;
    float acc[4][4];
    #pragma unroll
    for (int i=0;i<4;i++)
        #pragma unroll
        for (int j=0;j<4;j++) acc[i][j]=0.f;
    int ty = tid >> 4, tx = tid & 15;
    for (int k0 = 0; k0 < DD; k0 += BK){
        {
            int row = tid >> 2;
            int kq  = (tid & 3) * 4;
            float4 v = *reinterpret_cast<const float4*>(d_pooled + (size_t)(mBase+row)*DD + k0 + kq);
            As[kq+0][row]=v.x; As[kq+1][row]=v.y; As[kq+2][row]=v.z; As[kq+3][row]=v.w;
        }
        {
            int kb = tid >> 4;
            int nq = (tid & 15) * 4;
            *reinterpret_cast<float4*>(&Bs[kb][nq]) =
                *reinterpret_cast<const float4*>(d_sembT + (size_t)(k0+kb)*NST + nq);
        }
        __syncthreads();
        #pragma unroll
        for (int kk=0; kk<BK; kk++){
            float a[4], b[4];
            *reinterpret_cast<float4*>(a) = *reinterpret_cast<float4*>(&As[kk][ty*4]);
            *reinterpret_cast<float4*>(b) = *reinterpret_cast<float4*>(&Bs[kk][tx*4]);
            #pragma unroll
            for (int i=0;i<4;i++)
                #pragma unroll
                for (int j=0;j<4;j++) acc[i][j] += a[i]*b[j];
        }
        __syncthreads();
    }
    #pragma unroll
    for (int i=0;i<4;i++){
        int r = mBase + ty*4 + i;
        #pragma unroll
        for (int j=0;j<4;j++)
            out[(size_t)r*NST + tx*4 + j] = acc[i][j];
    }
}

// ---------------- launch ----------------
extern "C" void kernel_launch(void* const* d_in, const int* in_sizes, int n_in,
                              void* d_out, int out_size){
    const float* lstm_repr = (const float*)d_in[0];
    const float* Wih_f     = (const float*)d_in[1];
    const float* Whh_f     = (const float*)d_in[2];
    const float* b_f       = (const float*)d_in[3];
    const float* Wih_b     = (const float*)d_in[4];
    const float* Whh_b     = (const float*)d_in[5];
    const float* b_b       = (const float*)d_in[6];
    const float* slot_emb  = (const float*)d_in[7];
    const int*   bio       = (const int*)d_in[8];
    float* out = (float*)d_out;

    k_init<<<1, 32>>>();
    k_pack<<<BB, 64>>>(bio);
    k_prep<<<1024, 256>>>(Wih_f, Wih_b, b_f, b_b, Whh_f, Whh_b, slot_emb);

    // xg GEMM: N=2048/128=16 col tiles, M worst 32768/128=256 row tiles (early exit)
    k_xg_gemm<<<dim3(16, 256), 256>>>(lstm_repr);

    k_step0<<<dim3(NSPAN, 2), HH>>>();
    for (int t = 1; t < ML; t++){
        k_step_gemm<<<dim3(16, 64, 2), 256>>>(t);   // N=1024/64, M worst 4096/64
        k_step<<<dim3(NSPAN, 2), HH>>>(t);
    }
    k_score<<<dim3(64), 256>>>(out);
}

// round 3
// speedup vs baseline: 1.1211x; 1.1211x over previous
#include <cuda_runtime.h>
#include <cuda_bf16.h>
#include <math.h>

// ---------------- problem constants ----------------
#define BB   64
#define TT   512
#define DD   512
#define HH   256
#define MS   64
#define ML   8
#define NST  64
#define G4   1024
#define NCOL 2048
#define NSPAN (BB*MS)        // 4096
#define NPOS  (NSPAN*ML)     // 32768

// ---------------- device scratch ----------------
__device__ int   d_nvalid;
__device__ int   d_actcount[8];
__device__ int   d_len_g[NSPAN];
__device__ int   d_srcidx_g[NPOS];
__device__ int   d_rowidx_g[NPOS];
__device__ int   d_actlist_g[8][NSPAN];
__device__ float d_Wt[DD*NCOL];              // reordered: col n = dir*1024 + j*4 + gate
__device__ float d_bcat[NCOL];
__device__ float d_WhhT[HH*NCOL];            // reordered same way
__device__ float d_sembT[DD*NST];
__device__ float d_XG[(size_t)NPOS*NCOL];    // gate-interleaved input gates
__device__ float d_hbuf[2][NSPAN*2*HH];      // ping-pong h (fixes cross-block WAR race)
__device__ float d_c[NSPAN*2*HH];
__device__ float d_pooled[NSPAN*2*HH];       // [span][dir*256+j]

__device__ __forceinline__ float sigf(float x){ return 1.0f/(1.0f+__expf(-x)); }

__device__ __forceinline__ void cp16(void* dst, const void* src){
    unsigned int d = (unsigned int)__cvta_generic_to_shared(dst);
    asm volatile("cp.async.cg.shared.global [%0], [%1], 16;\n" :: "r"(d), "l"(src));
}
__device__ __forceinline__ void cp_commit(){ asm volatile("cp.async.commit_group;\n"); }
__device__ __forceinline__ void cp_wait0(){ asm volatile("cp.async.wait_group 0;\n"); }

// ---------------- init ----------------
__global__ void k_init(){
    if (threadIdx.x == 0) d_nvalid = 0;
    if (threadIdx.x < 8)  d_actcount[threadIdx.x] = 0;
}

// ---------------- span packing ----------------
__global__ void k_pack(const int* __restrict__ bio){
    int b = blockIdx.x;
    __shared__ int s_tok[MS][ML];
    __shared__ int s_cnt[MS];
    int tid = threadIdx.x;          // 64
    s_cnt[tid] = 0;
    __syncthreads();
    if (tid == 0){
        int sid = -1;
        const int* bb = bio + b*TT;
        for (int t = 0; t < TT; t++){
            int tag = bb[t];
            if (tag == 1) sid++;
            if ((tag == 1 || tag == 2) && sid >= 0 && sid < MS){
                int r = s_cnt[sid];
                if (r < ML) s_tok[sid][r] = t;
                s_cnt[sid] = r + 1;
            }
        }
    }
    __syncthreads();
    int s = tid;
    int len = min(s_cnt[s], ML);
    int span = b*MS + s;
    d_len_g[span] = len;
    if (len > 0){
        int base = atomicAdd(&d_nvalid, len);
        for (int r = 0; r < len; r++){
            d_srcidx_g[base+r] = b*TT + s_tok[s][r];
            d_rowidx_g[base+r] = span*ML + r;
        }
        for (int t = 1; t < ML; t++){
            if (len > t){
                int k = atomicAdd(&d_actcount[t], 1);
                d_actlist_g[t][k] = span;
            }
        }
    }
}

// ---------------- weight prep: transpose + gate-interleave reorder ----------------
// new col n: dir = n>>10, r = n&1023, j = r>>2, g = r&3  ->  original row g*HH + j
__global__ void k_prep(const float* __restrict__ Wih_f, const float* __restrict__ Wih_b,
                       const float* __restrict__ bf,    const float* __restrict__ bbias,
                       const float* __restrict__ Whh_f, const float* __restrict__ Whh_b,
                       const float* __restrict__ semb){
    int i = blockIdx.x*blockDim.x + threadIdx.x;
    int stride = gridDim.x*blockDim.x;
    for (int idx = i; idx < DD*NCOL; idx += stride){
        int k = idx >> 11, n = idx & (NCOL-1);
        int dir = n >> 10, r = n & (G4-1);
        int row = (r & 3)*HH + (r >> 2);
        d_Wt[idx] = dir ? Wih_b[row*DD + k] : Wih_f[row*DD + k];
    }
    for (int idx = i; idx < HH*NCOL; idx += stride){
        int k = idx >> 11, n = idx & (NCOL-1);
        int dir = n >> 10, r = n & (G4-1);
        int row = (r & 3)*HH + (r >> 2);
        d_WhhT[idx] = dir ? Whh_b[row*HH + k] : Whh_f[row*HH + k];
    }
    for (int idx = i; idx < NCOL; idx += stride){
        int dir = idx >> 10, r = idx & (G4-1);
        int row = (r & 3)*HH + (r >> 2);
        d_bcat[idx] = dir ? bbias[row] : bf[row];
    }
    for (int idx = i; idx < DD*NST; idx += stride){
        int k = idx / NST, n = idx % NST;
        d_sembT[idx] = semb[n*DD + k];
    }
}

// ---------------- xg GEMM (double buffered): gathered X [M,512] x Wt [512,2048] ----------------
__global__ void __launch_bounds__(256, 2) k_xg_gemm(const float* __restrict__ X){
    const int BM=128, BN=128, BK=16;
    int M = d_nvalid;
    int mBase = blockIdx.y * BM;
    if (mBase >= M) return;
    int nBase = blockIdx.x * BN;
    __shared__ float As[2][BK][BM];
    __shared__ float Bs[2][BK][BN];
    __shared__ int sidx[BM];
    __shared__ int ridx[BM];
    int tid = threadIdx.x;
    if (tid < BM){
        int m = mBase + tid;
        bool v = (m < M);
        sidx[tid] = v ? d_srcidx_g[m]*DD : 0;
        ridx[tid] = v ? d_rowidx_g[m] : -1;
    }
    __syncthreads();

    int ty = tid >> 4, tx = tid & 15;
    int arow0 = (tid + 0*256) >> 2, akq0 = ((tid + 0*256) & 3) * 4;
    int arow1 = (tid + 1*256) >> 2, akq1 = ((tid + 1*256) & 3) * 4;
    int bkb0 = (tid + 0*256) >> 5, bnq0 = ((tid + 0*256) & 31) * 4;
    int bkb1 = (tid + 1*256) >> 5, bnq1 = ((tid + 1*256) & 31) * 4;

    float4 ar0, ar1;
    ar0 = *reinterpret_cast<const float4*>(X + sidx[arow0] + akq0);
    ar1 = *reinterpret_cast<const float4*>(X + sidx[arow1] + akq1);
    As[0][akq0+0][arow0]=ar0.x; As[0][akq0+1][arow0]=ar0.y; As[0][akq0+2][arow0]=ar0.z; As[0][akq0+3][arow0]=ar0.w;
    As[0][akq1+0][arow1]=ar1.x; As[0][akq1+1][arow1]=ar1.y; As[0][akq1+2][arow1]=ar1.z; As[0][akq1+3][arow1]=ar1.w;
    cp16(&Bs[0][bkb0][bnq0], d_Wt + (size_t)bkb0*NCOL + nBase + bnq0);
    cp16(&Bs[0][bkb1][bnq1], d_Wt + (size_t)bkb1*NCOL + nBase + bnq1);
    cp_commit();
    cp_wait0();
    __syncthreads();

    float acc[8][8];
    #pragma unroll
    for (int i=0;i<8;i++)
        #pragma unroll
        for (int j=0;j<8;j++) acc[i][j]=0.f;

    int p = 0;
    for (int k0 = 0; k0 < DD; k0 += BK){
        int kn = k0 + BK;
        if (kn < DD){
            cp16(&Bs[p^1][bkb0][bnq0], d_Wt + (size_t)(kn+bkb0)*NCOL + nBase + bnq0);
            cp16(&Bs[p^1][bkb1][bnq1], d_Wt + (size_t)(kn+bkb1)*NCOL + nBase + bnq1);
            cp_commit();
            ar0 = *reinterpret_cast<const float4*>(X + sidx[arow0] + kn + akq0);
            ar1 = *reinterpret_cast<const float4*>(X + sidx[arow1] + kn + akq1);
        }
        #pragma unroll
        for (int kk = 0; kk < BK; kk++){
            float a[8], b[8];
            *reinterpret_cast<float4*>(a)   = *reinterpret_cast<float4*>(&As[p][kk][ty*8]);
            *reinterpret_cast<float4*>(a+4) = *reinterpret_cast<float4*>(&As[p][kk][ty*8+4]);
            *reinterpret_cast<float4*>(b)   = *reinterpret_cast<float4*>(&Bs[p][kk][tx*8]);
            *reinterpret_cast<float4*>(b+4) = *reinterpret_cast<float4*>(&Bs[p][kk][tx*8+4]);
            #pragma unroll
            for (int i=0;i<8;i++)
                #pragma unroll
                for (int j=0;j<8;j++) acc[i][j] += a[i]*b[j];
        }
        if (kn < DD){
            As[p^1][akq0+0][arow0]=ar0.x; As[p^1][akq0+1][arow0]=ar0.y; As[p^1][akq0+2][arow0]=ar0.z; As[p^1][akq0+3][arow0]=ar0.w;
            As[p^1][akq1+0][arow1]=ar1.x; As[p^1][akq1+1][arow1]=ar1.y; As[p^1][akq1+2][arow1]=ar1.z; As[p^1][akq1+3][arow1]=ar1.w;
            cp_wait0();
        }
        __syncthreads();
        p ^= 1;
    }
    float bias[8];
    *reinterpret_cast<float4*>(bias)   = *reinterpret_cast<const float4*>(d_bcat + nBase + tx*8);
    *reinterpret_cast<float4*>(bias+4) = *reinterpret_cast<const float4*>(d_bcat + nBase + tx*8 + 4);
    #pragma unroll
    for (int i=0;i<8;i++){
        int r = ty*8 + i;
        int crow = ridx[r];
        if (crow < 0) continue;
        float* dst = d_XG + (size_t)crow*NCOL + nBase + tx*8;
        float4 o0 = make_float4(acc[i][0]+bias[0], acc[i][1]+bias[1], acc[i][2]+bias[2], acc[i][3]+bias[3]);
        float4 o1 = make_float4(acc[i][4]+bias[4], acc[i][5]+bias[5], acc[i][6]+bias[6], acc[i][7]+bias[7]);
        *reinterpret_cast<float4*>(dst)   = o0;
        *reinterpret_cast<float4*>(dst+4) = o1;
    }
}

// ---------------- LSTM step 0 (pointwise only) -> writes h buffer 0 ----------------
__global__ void k_step0(){
    int span = blockIdx.x;
    int dir  = blockIdx.y;
    int j    = threadIdx.x;
    int len  = d_len_g[span];
    int hidx = (span*2 + dir)*HH + j;
    if (len == 0){
        d_hbuf[0][hidx] = 0.f; d_c[hidx] = 0.f; d_pooled[hidx] = 0.f;
        return;
    }
    int rank = dir ? (len-1) : 0;
    float4 g = *reinterpret_cast<const float4*>(
        d_XG + (size_t)(span*ML + rank)*NCOL + dir*G4 + j*4);
    float c = sigf(g.x) * tanhf(g.z);
    float h = sigf(g.w) * tanhf(c);
    d_c[hidx] = c; d_hbuf[0][hidx] = h; d_pooled[hidx] = h;
}

// ---------------- fused recurrent GEMM + LSTM pointwise epilogue ----------------
// reads h from d_hbuf[(t-1)&1], writes h to d_hbuf[t&1] -> no cross-block WAR race
__global__ void __launch_bounds__(256, 2) k_rec(int t){
    const int BM=64, BN=256, BK=16;
    int cnt = d_actcount[t];
    int mBase = blockIdx.y * BM;
    if (mBase >= cnt) return;
    int dir = blockIdx.z;
    int nBase = blockIdx.x * BN;             // within this dir's 1024 cols
    const float* __restrict__ h_r = d_hbuf[(t-1)&1];
    float* __restrict__ h_w = d_hbuf[t&1];
    __shared__ float As[2][BK][BM];
    __shared__ float Bs[2][BK][BN];
    __shared__ int aoff[BM];
    __shared__ int spn[BM];
    __shared__ int slen[BM];
    int tid = threadIdx.x;
    if (tid < BM){
        int m = mBase + tid;
        bool v = (m < cnt);
        int span = v ? d_actlist_g[t][m] : 0;
        aoff[tid] = (span*2 + dir)*HH;
        spn[tid]  = v ? span : -1;
        slen[tid] = d_len_g[span];
    }
    __syncthreads();

    int ty = tid >> 5, tx = tid & 31;        // rows ty*8, cols tx*8
    int arow = tid >> 2, akq = (tid & 3) * 4;
    const float* Wbase = d_WhhT + dir*G4 + nBase;

    float4 ar;
    ar = *reinterpret_cast<const float4*>(h_r + aoff[arow] + akq);
    As[0][akq+0][arow]=ar.x; As[0][akq+1][arow]=ar.y; As[0][akq+2][arow]=ar.z; As[0][akq+3][arow]=ar.w;
    #pragma unroll
    for (int li = 0; li < 4; li++){
        int lin = tid + li*256;
        int kb = lin >> 6, nq = (lin & 63) * 4;
        cp16(&Bs[0][kb][nq], Wbase + (size_t)kb*NCOL + nq);
    }
    cp_commit();
    cp_wait0();
    __syncthreads();

    float acc[8][8];
    #pragma unroll
    for (int i=0;i<8;i++)
        #pragma unroll
        for (int j=0;j<8;j++) acc[i][j]=0.f;

    int p = 0;
    for (int k0 = 0; k0 < HH; k0 += BK){
        int kn = k0 + BK;
        if (kn < HH){
            #pragma unroll
            for (int li = 0; li < 4; li++){
                int lin = tid + li*256;
                int kb = lin >> 6, nq = (lin & 63) * 4;
                cp16(&Bs[p^1][kb][nq], Wbase + (size_t)(kn+kb)*NCOL + nq);
            }
            cp_commit();
            ar = *reinterpret_cast<const float4*>(h_r + aoff[arow] + kn + akq);
        }
        #pragma unroll
        for (int kk = 0; kk < BK; kk++){
            float a[8], b[8];
            *reinterpret_cast<float4*>(a)   = *reinterpret_cast<float4*>(&As[p][kk][ty*8]);
            *reinterpret_cast<float4*>(a+4) = *reinterpret_cast<float4*>(&As[p][kk][ty*8+4]);
            *reinterpret_cast<float4*>(b)   = *reinterpret_cast<float4*>(&Bs[p][kk][tx*8]);
            *reinterpret_cast<float4*>(b+4) = *reinterpret_cast<float4*>(&Bs[p][kk][tx*8+4]);
            #pragma unroll
            for (int i=0;i<8;i++)
                #pragma unroll
                for (int j=0;j<8;j++) acc[i][j] += a[i]*b[j];
        }
        if (kn < HH){
            As[p^1][akq+0][arow]=ar.x; As[p^1][akq+1][arow]=ar.y; As[p^1][akq+2][arow]=ar.z; As[p^1][akq+3][arow]=ar.w;
            cp_wait0();
        }
        __syncthreads();
        p ^= 1;
    }

    // fused LSTM pointwise epilogue: cols tx*8 = 2 hidden units x 4 gates
    int j0 = (nBase + tx*8) >> 2;
    #pragma unroll
    for (int i=0;i<8;i++){
        int r = ty*8 + i;
        int span = spn[r];
        if (span < 0) continue;
        int rank = dir ? (slen[r]-1-t) : t;
        const float* xg = d_XG + (size_t)(span*ML + rank)*NCOL + dir*G4 + nBase + tx*8;
        float4 x0 = *reinterpret_cast<const float4*>(xg);
        float4 x1 = *reinterpret_cast<const float4*>(xg+4);
        int hbase = (span*2 + dir)*HH + j0;
        float c0 = d_c[hbase], c1 = d_c[hbase+1];
        float gi0 = acc[i][0]+x0.x, gf0 = acc[i][1]+x0.y, gg0 = acc[i][2]+x0.z, go0 = acc[i][3]+x0.w;
        float gi1 = acc[i][4]+x1.x, gf1 = acc[i][5]+x1.y, gg1 = acc[i][6]+x1.z, go1 = acc[i][7]+x1.w;
        c0 = sigf(gf0)*c0 + sigf(gi0)*tanhf(gg0);
        c1 = sigf(gf1)*c1 + sigf(gi1)*tanhf(gg1);
        float h0 = sigf(go0)*tanhf(c0);
        float h1 = sigf(go1)*tanhf(c1);
        d_c[hbase] = c0;  d_c[hbase+1] = c1;
        h_w[hbase] = h0;  h_w[hbase+1] = h1;
        d_pooled[hbase]   += h0;
        d_pooled[hbase+1] += h1;
    }
}

// ---------------- scoring GEMM: pooled [4096,512] x sembT [512,64] ----------------
__global__ void k_score(float* __restrict__ out){
    const int BM=64, BN=64, BK=16;
    int mBase = blockIdx.x * BM;
    __shared__ float As[BK][BM];
    __shared__ float Bs[BK][BN];
    int tid = threadIdx.x;
    float acc[4][4];
    #pragma unroll
    for (int i=0;i<4;i++)
        #pragma unroll
        for (int j=0;j<4;j++) acc[i][j]=0.f;
    int ty = tid >> 4, tx = tid & 15;
    for (int k0 = 0; k0 < DD; k0 += BK){
        {
            int row = tid >> 2;
            int kq  = (tid & 3) * 4;
            float4 v = *reinterpret_cast<const float4*>(d_pooled + (size_t)(mBase+row)*DD + k0 + kq);
            As[kq+0][row]=v.x; As[kq+1][row]=v.y; As[kq+2][row]=v.z; As[kq+3][row]=v.w;
        }
        {
            int kb = tid >> 4;
            int nq = (tid & 15) * 4;
            *reinterpret_cast<float4*>(&Bs[kb][nq]) =
                *reinterpret_cast<const float4*>(d_sembT + (size_t)(k0+kb)*NST + nq);
        }
        __syncthreads();
        #pragma unroll
        for (int kk=0; kk<BK; kk++){
            float a[4], b[4];
            *reinterpret_cast<float4*>(a) = *reinterpret_cast<float4*>(&As[kk][ty*4]);
            *reinterpret_cast<float4*>(b) = *reinterpret_cast<float4*>(&Bs[kk][tx*4]);
            #pragma unroll
            for (int i=0;i<4;i++)
                #pragma unroll
                for (int j=0;j<4;j++) acc[i][j] += a[i]*b[j];
        }
        __syncthreads();
    }
    #pragma unroll
    for (int i=0;i<4;i++){
        int r = mBase + ty*4 + i;
        #pragma unroll
        for (int j=0;j<4;j++)
            out[(size_t)r*NST + tx*4 + j] = acc[i][j];
    }
}

// ---------------- launch ----------------
extern "C" void kernel_launch(void* const* d_in, const int* in_sizes, int n_in,
                              void* d_out, int out_size){
    const float* lstm_repr = (const float*)d_in[0];
    const float* Wih_f     = (const float*)d_in[1];
    const float* Whh_f     = (const float*)d_in[2];
    const float* b_f       = (const float*)d_in[3];
    const float* Wih_b     = (const float*)d_in[4];
    const float* Whh_b     = (const float*)d_in[5];
    const float* b_b       = (const float*)d_in[6];
    const float* slot_emb  = (const float*)d_in[7];
    const int*   bio       = (const int*)d_in[8];
    float* out = (float*)d_out;

    k_init<<<1, 32>>>();
    k_pack<<<BB, 64>>>(bio);
    k_prep<<<1024, 256>>>(Wih_f, Wih_b, b_f, b_b, Whh_f, Whh_b, slot_emb);

    k_xg_gemm<<<dim3(16, 256), 256>>>(lstm_repr);

    k_step0<<<dim3(NSPAN, 2), HH>>>();
    for (int t = 1; t < ML; t++){
        k_rec<<<dim3(4, 64, 2), 256>>>(t);
    }
    k_score<<<dim3(64), 256>>>(out);
}

// round 6
// speedup vs baseline: 1.5073x; 1.3444x over previous
#include <cuda_runtime.h>
#include <cuda_bf16.h>
#include <math.h>
#include <cstdint>

// ---------------- problem constants ----------------
#define BB   64
#define TT   512
#define DD   512
#define HH   256
#define MS   64
#define ML   8
#define NST  64
#define G4   1024
#define NCOL 2048
#define NSPAN (BB*MS)        // 4096
#define NPOS  (NSPAN*ML)     // 32768

// ---------------- device scratch ----------------
__device__ int   d_nvalid;
__device__ int   d_actcount[8];
__device__ int   d_len_g[NSPAN];
__device__ int   d_srcidx_g[NPOS];
__device__ int   d_rowidx_g[NPOS];
__device__ int   d_actlist_g[8][NSPAN];
__device__ __nv_bfloat16 d_Wh[(size_t)NCOL*DD];   // W_ih hi split, row n (gate-interleaved), col k
__device__ __nv_bfloat16 d_Wl[(size_t)NCOL*DD];   // lo split
__device__ float d_bcat[NCOL];
__device__ float d_WhhT[HH*NCOL];            // [k][dir*1024 + j*4 + gate]
__device__ float d_sembT[DD*NST];
__device__ float d_XG[(size_t)NPOS*NCOL];    // gate-interleaved input gates
__device__ float d_hbuf[2][NSPAN*2*HH];      // ping-pong h
__device__ float d_c[NSPAN*2*HH];
__device__ float d_pooled[NSPAN*2*HH];

__device__ __forceinline__ float sigf(float x){ return 1.0f/(1.0f+__expf(-x)); }

__device__ __forceinline__ void cp16(void* dst, const void* src){
    unsigned int d = (unsigned int)__cvta_generic_to_shared(dst);
    asm volatile("cp.async.cg.shared.global [%0], [%1], 16;\n" :: "r"(d), "l"(src));
}
__device__ __forceinline__ void cp_commit(){ asm volatile("cp.async.commit_group;\n"); }
__device__ __forceinline__ void cp_wait0(){ asm volatile("cp.async.wait_group 0;\n"); }

__device__ __forceinline__ uint32_t smem_u32(const void* p){
    uint32_t a;
    asm("{ .reg .u64 t; cvta.to.shared.u64 t, %1; cvt.u32.u64 %0, t; }" : "=r"(a) : "l"(p));
    return a;
}
__device__ __forceinline__ void ldm4(uint32_t* r, uint32_t addr){
    asm volatile("ldmatrix.sync.aligned.m8n8.x4.shared.b16 {%0,%1,%2,%3}, [%4];"
        : "=r"(r[0]),"=r"(r[1]),"=r"(r[2]),"=r"(r[3]) : "r"(addr));
}
__device__ __forceinline__ void mma16816(float* c, const uint32_t* a, const uint32_t* b){
    asm volatile("mma.sync.aligned.m16n8k16.row.col.f32.bf16.bf16.f32 "
        "{%0,%1,%2,%3}, {%4,%5,%6,%7}, {%8,%9}, {%0,%1,%2,%3};"
        : "+f"(c[0]),"+f"(c[1]),"+f"(c[2]),"+f"(c[3])
        : "r"(a[0]),"r"(a[1]),"r"(a[2]),"r"(a[3]), "r"(b[0]),"r"(b[1]));
}

// ---------------- init ----------------
__global__ void k_init(){
    if (threadIdx.x == 0) d_nvalid = 0;
    if (threadIdx.x < 8)  d_actcount[threadIdx.x] = 0;
}

// ---------------- span packing ----------------
__global__ void k_pack(const int* __restrict__ bio){
    int b = blockIdx.x;
    __shared__ int s_tok[MS][ML];
    __shared__ int s_cnt[MS];
    int tid = threadIdx.x;          // 64
    s_cnt[tid] = 0;
    __syncthreads();
    if (tid == 0){
        int sid = -1;
        const int* bb = bio + b*TT;
        for (int t = 0; t < TT; t++){
            int tag = bb[t];
            if (tag == 1) sid++;
            if ((tag == 1 || tag == 2) && sid >= 0 && sid < MS){
                int r = s_cnt[sid];
                if (r < ML) s_tok[sid][r] = t;
                s_cnt[sid] = r + 1;
            }
        }
    }
    __syncthreads();
    int s = tid;
    int len = min(s_cnt[s], ML);
    int span = b*MS + s;
    d_len_g[span] = len;
    if (len > 0){
        int base = atomicAdd(&d_nvalid, len);
        for (int r = 0; r < len; r++){
            d_srcidx_g[base+r] = b*TT + s_tok[s][r];
            d_rowidx_g[base+r] = span*ML + r;
        }
        for (int t = 1; t < ML; t++){
            if (len > t){
                int k = atomicAdd(&d_actcount[t], 1);
                d_actlist_g[t][k] = span;
            }
        }
    }
}

// ---------------- weight prep ----------------
// gate-interleaved col n: dir = n>>10, r = n&1023 -> original row (r&3)*HH + (r>>2)
__global__ void k_prep(const float* __restrict__ Wih_f, const float* __restrict__ Wih_b,
                       const float* __restrict__ bf,    const float* __restrict__ bbias,
                       const float* __restrict__ Whh_f, const float* __restrict__ Whh_b,
                       const float* __restrict__ semb){
    int i = blockIdx.x*blockDim.x + threadIdx.x;
    int stride = gridDim.x*blockDim.x;
    for (int idx = i; idx < NCOL*DD; idx += stride){
        int n = idx / DD, k = idx % DD;
        int dir = n >> 10, r = n & (G4-1);
        int row = (r & 3)*HH + (r >> 2);
        float w = dir ? Wih_b[row*DD + k] : Wih_f[row*DD + k];
        __nv_bfloat16 h = __float2bfloat16(w);
        d_Wh[idx] = h;
        d_Wl[idx] = __float2bfloat16(w - __bfloat162float(h));
    }
    for (int idx = i; idx < HH*NCOL; idx += stride){
        int k = idx >> 11, n = idx & (NCOL-1);
        int dir = n >> 10, r = n & (G4-1);
        int row = (r & 3)*HH + (r >> 2);
        d_WhhT[idx] = dir ? Whh_b[row*HH + k] : Whh_f[row*HH + k];
    }
    for (int idx = i; idx < NCOL; idx += stride){
        int dir = idx >> 10, r = idx & (G4-1);
        int row = (r & 3)*HH + (r >> 2);
        d_bcat[idx] = dir ? bbias[row] : bf[row];
    }
    for (int idx = i; idx < DD*NST; idx += stride){
        int k = idx / NST, n = idx % NST;
        d_sembT[idx] = semb[n*DD + k];
    }
}

// ---------------- xg GEMM via mma.sync bf16 3-pass split ----------------
// CTA tile 128x128, K-chunk 32. 8 warps, warp tile 32x64.
// SMEM rows padded to 40 bf16 (80 B) -> conflict-free ldmatrix.
#define XPAD 40
#define ABUF (128*XPAD)      // elements per buffer

__global__ void __launch_bounds__(256) k_xg_mma(const float* __restrict__ X){
    int M = d_nvalid;
    int mBase = blockIdx.y * 128;
    if (mBase >= M) return;
    int nBase = blockIdx.x * 128;

    extern __shared__ __nv_bfloat16 sm[];
    __nv_bfloat16* Ah = sm;                  // [2][128][XPAD]
    __nv_bfloat16* Al = Ah + 2*ABUF;
    __nv_bfloat16* Bh = Al + 2*ABUF;
    __nv_bfloat16* Bl = Bh + 2*ABUF;
    int* s_sidx = (int*)(Bl + 2*ABUF);
    int* s_ridx = s_sidx + 128;

    int tid = threadIdx.x;
    if (tid < 128){
        int m = mBase + tid;
        bool v = (m < M);
        s_sidx[tid] = v ? d_srcidx_g[m]*DD : 0;
        s_ridx[tid] = v ? d_rowidx_g[m] : -1;
    }
    __syncthreads();

    int lane = tid & 31, w = tid >> 5;
    int wm = w & 3, wn = w >> 2;             // warp tile: rows wm*32, cols wn*64

    // loader assignment: thread -> (row, half) ; half covers 16 elements of the 32-wide k-chunk
    int lrow = tid >> 1, lhalf = tid & 1;
    int aoffs = lrow*XPAD + lhalf*16;        // smem element offset for this thread's slab
    const __nv_bfloat16* BhSrc = d_Wh + (size_t)(nBase + lrow)*DD + lhalf*16;
    const __nv_bfloat16* BlSrc = d_Wl + (size_t)(nBase + lrow)*DD + lhalf*16;
    const float* ASrc = X + s_sidx[lrow] + lhalf*16;

    // ldmatrix addresses (element offsets computed per use)
    int aRowOff = lane & 15;                 // within 16-row tile
    int aKOff   = (lane >> 4) * 8;
    int bNOff   = (lane & 7) + ((lane >> 4) << 3);
    int bKOff   = ((lane >> 3) & 1) * 8;

    uint32_t smbA_h = smem_u32(Ah), smbA_l = smem_u32(Al);
    uint32_t smbB_h = smem_u32(Bh), smbB_l = smem_u32(Bl);

    float acc[2][8][4];
    #pragma unroll
    for (int i=0;i<2;i++)
        #pragma unroll
        for (int j=0;j<8;j++)
            #pragma unroll
            for (int q=0;q<4;q++) acc[i][j][q]=0.f;

    // ---- prologue: fill buffer 0 (kc = 0) ----
    {
        cp16(Bh + aoffs, BhSrc);       cp16(Bh + aoffs + 8, BhSrc + 8);
        cp16(Bl + aoffs, BlSrc);       cp16(Bl + aoffs + 8, BlSrc + 8);
        cp_commit();
        float4 v0 = *(const float4*)(ASrc + 0);
        float4 v1 = *(const float4*)(ASrc + 4);
        float4 v2 = *(const float4*)(ASrc + 8);
        float4 v3 = *(const float4*)(ASrc + 12);
        float fv[16] = {v0.x,v0.y,v0.z,v0.w, v1.x,v1.y,v1.z,v1.w,
                        v2.x,v2.y,v2.z,v2.w, v3.x,v3.y,v3.z,v3.w};
        __nv_bfloat16 hh[16], ll[16];
        #pragma unroll
        for (int q=0;q<16;q++){
            hh[q] = __float2bfloat16(fv[q]);
            ll[q] = __float2bfloat16(fv[q] - __bfloat162float(hh[q]));
        }
        *(uint4*)(Ah + aoffs)     = *(uint4*)(hh);
        *(uint4*)(Ah + aoffs + 8) = *(uint4*)(hh+8);
        *(uint4*)(Al + aoffs)     = *(uint4*)(ll);
        *(uint4*)(Al + aoffs + 8) = *(uint4*)(ll+8);
        cp_wait0();
        __syncthreads();
    }

    int p = 0;
    for (int kc = 0; kc < 16; kc++){
        // issue next-buffer loads
        float fv[16];
        bool more = (kc < 15);
        if (more){
            int nb = p ^ 1;
            int k0 = (kc+1)*32;
            int doffs = nb*ABUF + aoffs;
            cp16(Bh + doffs, BhSrc + k0);       cp16(Bh + doffs + 8, BhSrc + k0 + 8);
            cp16(Bl + doffs, BlSrc + k0);       cp16(Bl + doffs + 8, BlSrc + k0 + 8);
            cp_commit();
            float4 v0 = *(const float4*)(ASrc + k0 + 0);
            float4 v1 = *(const float4*)(ASrc + k0 + 4);
            float4 v2 = *(const float4*)(ASrc + k0 + 8);
            float4 v3 = *(const float4*)(ASrc + k0 + 12);
            fv[0]=v0.x; fv[1]=v0.y; fv[2]=v0.z; fv[3]=v0.w;
            fv[4]=v1.x; fv[5]=v1.y; fv[6]=v1.z; fv[7]=v1.w;
            fv[8]=v2.x; fv[9]=v2.y; fv[10]=v2.z; fv[11]=v2.w;
            fv[12]=v3.x; fv[13]=v3.y; fv[14]=v3.z; fv[15]=v3.w;
        }

        // ---- compute on buffer p ----
        uint32_t baseAh = smbA_h + p*ABUF*2;
        uint32_t baseAl = smbA_l + p*ABUF*2;
        uint32_t baseBh = smbB_h + p*ABUF*2;
        uint32_t baseBl = smbB_l + p*ABUF*2;
        #pragma unroll
        for (int ks = 0; ks < 2; ks++){
            uint32_t ah[2][4], al[2][4];
            #pragma unroll
            for (int mt = 0; mt < 2; mt++){
                uint32_t eo = ((wm*32 + mt*16 + aRowOff)*XPAD + ks*16 + aKOff)*2;
                ldm4(ah[mt], baseAh + eo);
                ldm4(al[mt], baseAl + eo);
            }
            uint32_t bh[8][2], bl[8][2];
            #pragma unroll
            for (int g = 0; g < 4; g++){
                uint32_t eo = ((wn*64 + g*16 + bNOff)*XPAD + ks*16 + bKOff)*2;
                uint32_t r[4];
                ldm4(r, baseBh + eo);
                bh[2*g][0]=r[0]; bh[2*g][1]=r[1]; bh[2*g+1][0]=r[2]; bh[2*g+1][1]=r[3];
                ldm4(r, baseBl + eo);
                bl[2*g][0]=r[0]; bl[2*g][1]=r[1]; bl[2*g+1][0]=r[2]; bl[2*g+1][1]=r[3];
            }
            #pragma unroll
            for (int mt = 0; mt < 2; mt++)
                #pragma unroll
                for (int nt = 0; nt < 8; nt++){
                    mma16816(acc[mt][nt], ah[mt], bh[nt]);
                    mma16816(acc[mt][nt], ah[mt], bl[nt]);
                    mma16816(acc[mt][nt], al[mt], bh[nt]);
                }
        }

        if (more){
            int nb = p ^ 1;
            int doffs = nb*ABUF + aoffs;
            __nv_bfloat16 hh[16], ll[16];
            #pragma unroll
            for (int q=0;q<16;q++){
                hh[q] = __float2bfloat16(fv[q]);
                ll[q] = __float2bfloat16(fv[q] - __bfloat162float(hh[q]));
            }
            *(uint4*)(Ah + doffs)     = *(uint4*)(hh);
            *(uint4*)(Ah + doffs + 8) = *(uint4*)(hh+8);
            *(uint4*)(Al + doffs)     = *(uint4*)(ll);
            *(uint4*)(Al + doffs + 8) = *(uint4*)(ll+8);
            cp_wait0();
        }
        __syncthreads();
        p ^= 1;
    }

    // ---- epilogue: bias + scatter store ----
    #pragma unroll
    for (int mt = 0; mt < 2; mt++){
        int rl0 = wm*32 + mt*16 + (lane >> 2);
        #pragma unroll
        for (int half = 0; half < 2; half++){
            int rl = rl0 + half*8;
            int grow = s_ridx[rl];
            if (grow < 0) continue;
            float* dst = d_XG + (size_t)grow*NCOL + nBase;
            #pragma unroll
            for (int nt = 0; nt < 8; nt++){
                int col = wn*64 + nt*8 + (lane & 3)*2;
                float2 b2 = *(const float2*)(d_bcat + nBase + col);
                float2 o;
                o.x = acc[mt][nt][half*2+0] + b2.x;
                o.y = acc[mt][nt][half*2+1] + b2.y;
                *(float2*)(dst + col) = o;
            }
        }
    }
}
#define XSM_BYTES (8*ABUF*2 + 256*4)

// ---------------- LSTM step 0 -> writes h buffer 0 ----------------
__global__ void k_step0(){
    int span = blockIdx.x;
    int dir  = blockIdx.y;
    int j    = threadIdx.x;
    int len  = d_len_g[span];
    int hidx = (span*2 + dir)*HH + j;
    if (len == 0){
        d_hbuf[0][hidx] = 0.f; d_c[hidx] = 0.f; d_pooled[hidx] = 0.f;
        return;
    }
    int rank = dir ? (len-1) : 0;
    float4 g = *reinterpret_cast<const float4*>(
        d_XG + (size_t)(span*ML + rank)*NCOL + dir*G4 + j*4);
    float c = sigf(g.x) * tanhf(g.z);
    float h = sigf(g.w) * tanhf(c);
    d_c[hidx] = c; d_hbuf[0][hidx] = h; d_pooled[hidx] = h;
}

// ---------------- fused recurrent GEMM + LSTM pointwise epilogue ----------------
__global__ void __launch_bounds__(256, 2) k_rec(int t){
    const int BM=64, BN=256, BK=16;
    int cnt = d_actcount[t];
    int mBase = blockIdx.y * BM;
    if (mBase >= cnt) return;
    int dir = blockIdx.z;
    int nBase = blockIdx.x * BN;
    const float* __restrict__ h_r = d_hbuf[(t-1)&1];
    float* __restrict__ h_w = d_hbuf[t&1];
    __shared__ float As[2][BK][BM];
    __shared__ float Bs[2][BK][BN];
    __shared__ int aoff[BM];
    __shared__ int spn[BM];
    __shared__ int slen[BM];
    int tid = threadIdx.x;
    if (tid < BM){
        int m = mBase + tid;
        bool v = (m < cnt);
        int span = v ? d_actlist_g[t][m] : 0;
        aoff[tid] = (span*2 + dir)*HH;
        spn[tid]  = v ? span : -1;
        slen[tid] = d_len_g[span];
    }
    __syncthreads();

    int ty = tid >> 5, tx = tid & 31;
    int arow = tid >> 2, akq = (tid & 3) * 4;
    const float* Wbase = d_WhhT + dir*G4 + nBase;

    float4 ar;
    ar = *reinterpret_cast<const float4*>(h_r + aoff[arow] + akq);
    As[0][akq+0][arow]=ar.x; As[0][akq+1][arow]=ar.y; As[0][akq+2][arow]=ar.z; As[0][akq+3][arow]=ar.w;
    #pragma unroll
    for (int li = 0; li < 4; li++){
        int lin = tid + li*256;
        int kb = lin >> 6, nq = (lin & 63) * 4;
        cp16(&Bs[0][kb][nq], Wbase + (size_t)kb*NCOL + nq);
    }
    cp_commit();
    cp_wait0();
    __syncthreads();

    float acc[8][8];
    #pragma unroll
    for (int i=0;i<8;i++)
        #pragma unroll
        for (int j=0;j<8;j++) acc[i][j]=0.f;

    int p = 0;
    for (int k0 = 0; k0 < HH; k0 += BK){
        int kn = k0 + BK;
        if (kn < HH){
            #pragma unroll
            for (int li = 0; li < 4; li++){
                int lin = tid + li*256;
                int kb = lin >> 6, nq = (lin & 63) * 4;
                cp16(&Bs[p^1][kb][nq], Wbase + (size_t)(kn+kb)*NCOL + nq);
            }
            cp_commit();
            ar = *reinterpret_cast<const float4*>(h_r + aoff[arow] + kn + akq);
        }
        #pragma unroll
        for (int kk = 0; kk < BK; kk++){
            float a[8], b[8];
            *reinterpret_cast<float4*>(a)   = *reinterpret_cast<float4*>(&As[p][kk][ty*8]);
            *reinterpret_cast<float4*>(a+4) = *reinterpret_cast<float4*>(&As[p][kk][ty*8+4]);
            *reinterpret_cast<float4*>(b)   = *reinterpret_cast<float4*>(&Bs[p][kk][tx*8]);
            *reinterpret_cast<float4*>(b+4) = *reinterpret_cast<float4*>(&Bs[p][kk][tx*8+4]);
            #pragma unroll
            for (int i=0;i<8;i++)
                #pragma unroll
                for (int j=0;j<8;j++) acc[i][j] += a[i]*b[j];
        }
        if (kn < HH){
            As[p^1][akq+0][arow]=ar.x; As[p^1][akq+1][arow]=ar.y; As[p^1][akq+2][arow]=ar.z; As[p^1][akq+3][arow]=ar.w;
            cp_wait0();
        }
        __syncthreads();
        p ^= 1;
    }

    int j0 = (nBase + tx*8) >> 2;
    #pragma unroll
    for (int i=0;i<8;i++){
        int r = ty*8 + i;
        int span = spn[r];
        if (span < 0) continue;
        int rank = dir ? (slen[r]-1-t) : t;
        const float* xg = d_XG + (size_t)(span*ML + rank)*NCOL + dir*G4 + nBase + tx*8;
        float4 x0 = *reinterpret_cast<const float4*>(xg);
        float4 x1 = *reinterpret_cast<const float4*>(xg+4);
        int hbase = (span*2 + dir)*HH + j0;
        float c0 = d_c[hbase], c1 = d_c[hbase+1];
        float gi0 = acc[i][0]+x0.x, gf0 = acc[i][1]+x0.y, gg0 = acc[i][2]+x0.z, go0 = acc[i][3]+x0.w;
        float gi1 = acc[i][4]+x1.x, gf1 = acc[i][5]+x1.y, gg1 = acc[i][6]+x1.z, go1 = acc[i][7]+x1.w;
        c0 = sigf(gf0)*c0 + sigf(gi0)*tanhf(gg0);
        c1 = sigf(gf1)*c1 + sigf(gi1)*tanhf(gg1);
        float h0 = sigf(go0)*tanhf(c0);
        float h1 = sigf(go1)*tanhf(c1);
        d_c[hbase] = c0;  d_c[hbase+1] = c1;
        h_w[hbase] = h0;  h_w[hbase+1] = h1;
        d_pooled[hbase]   += h0;
        d_pooled[hbase+1] += h1;
    }
}

// ---------------- scoring GEMM: pooled [4096,512] x sembT [512,64] ----------------
__global__ void k_score(float* __restrict__ out){
    const int BM=64, BN=64, BK=16;
    int mBase = blockIdx.x * BM;
    __shared__ float As[BK][BM];
    __shared__ float Bs[BK][BN];
    int tid = threadIdx.x;
    float acc[4][4];
    #pragma unroll
    for (int i=0;i<4;i++)
        #pragma unroll
        for (int j=0;j<4;j++) acc[i][j]=0.f;
    int ty = tid >> 4, tx = tid & 15;
    for (int k0 = 0; k0 < DD; k0 += BK){
        {
            int row = tid >> 2;
            int kq  = (tid & 3) * 4;
            float4 v = *reinterpret_cast<const float4*>(d_pooled + (size_t)(mBase+row)*DD + k0 + kq);
            As[kq+0][row]=v.x; As[kq+1][row]=v.y; As[kq+2][row]=v.z; As[kq+3][row]=v.w;
        }
        {
            int kb = tid >> 4;
            int nq = (tid & 15) * 4;
            *reinterpret_cast<float4*>(&Bs[kb][nq]) =
                *reinterpret_cast<const float4*>(d_sembT + (size_t)(k0+kb)*NST + nq);
        }
        __syncthreads();
        #pragma unroll
        for (int kk=0; kk<BK; kk++){
            float a[4], b[4];
            *reinterpret_cast<float4*>(a) = *reinterpret_cast<float4*>(&As[kk][ty*4]);
            *reinterpret_cast<float4*>(b) = *reinterpret_cast<float4*>(&Bs[kk][tx*4]);
            #pragma unroll
            for (int i=0;i<4;i++)
                #pragma unroll
                for (int j=0;j<4;j++) acc[i][j] += a[i]*b[j];
        }
        __syncthreads();
    }
    #pragma unroll
    for (int i=0;i<4;i++){
        int r = mBase + ty*4 + i;
        #pragma unroll
        for (int j=0;j<4;j++)
            out[(size_t)r*NST + tx*4 + j] = acc[i][j];
    }
}

// ---------------- launch ----------------
extern "C" void kernel_launch(void* const* d_in, const int* in_sizes, int n_in,
                              void* d_out, int out_size){
    const float* lstm_repr = (const float*)d_in[0];
    const float* Wih_f     = (const float*)d_in[1];
    const float* Whh_f     = (const float*)d_in[2];
    const float* b_f       = (const float*)d_in[3];
    const float* Wih_b     = (const float*)d_in[4];
    const float* Whh_b     = (const float*)d_in[5];
    const float* b_b       = (const float*)d_in[6];
    const float* slot_emb  = (const float*)d_in[7];
    const int*   bio       = (const int*)d_in[8];
    float* out = (float*)d_out;

    cudaFuncSetAttribute(k_xg_mma, cudaFuncAttributeMaxDynamicSharedMemorySize, XSM_BYTES);

    k_init<<<1, 32>>>();
    k_pack<<<BB, 64>>>(bio);
    k_prep<<<1024, 256>>>(Wih_f, Wih_b, b_f, b_b, Whh_f, Whh_b, slot_emb);

    k_xg_mma<<<dim3(16, 256), 256, XSM_BYTES>>>(lstm_repr);

    k_step0<<<dim3(NSPAN, 2), HH>>>();
    for (int t = 1; t < ML; t++){
        k_rec<<<dim3(4, 64, 2), 256>>>(t);
    }
    k_score<<<dim3(64), 256>>>(out);
}